// round 1
// baseline (speedup 1.0000x reference)
#include <cuda_runtime.h>

#define IN_DIM   2048
#define OUT_DIM  14951
#define THREADS  256
#define EPS      1e-12f

__global__ __launch_bounds__(THREADS, 8)
void hadamard_classifier_kernel(const float* __restrict__ x,
                                const float* __restrict__ scale,
                                const float* __restrict__ bias,
                                float* __restrict__ out)
{
    __shared__ float s[IN_DIM];
    __shared__ float red[THREADS / 32];
    __shared__ float s_c;

    const int row = blockIdx.x;
    const int tid = threadIdx.x;

    // ---- Load row (float4, coalesced) + accumulate sum of squares ----
    const float4* xr = reinterpret_cast<const float4*>(x + (size_t)row * IN_DIM);
    float4* s4 = reinterpret_cast<float4*>(s);

    float ss = 0.0f;
#pragma unroll
    for (int k = 0; k < IN_DIM / 4 / THREADS; ++k) {   // 2 iterations
        float4 v = xr[tid + k * THREADS];
        s4[tid + k * THREADS] = v;
        ss += v.x * v.x + v.y * v.y + v.z * v.z + v.w * v.w;
    }

    // ---- Block reduction of ss ----
#pragma unroll
    for (int off = 16; off > 0; off >>= 1)
        ss += __shfl_xor_sync(0xFFFFFFFFu, ss, off);
    if ((tid & 31) == 0) red[tid >> 5] = ss;
    __syncthreads();
    if (tid == 0) {
        float total = 0.0f;
#pragma unroll
        for (int w = 0; w < THREADS / 32; ++w) total += red[w];
        float rn = rsqrtf(fmaxf(total, EPS));
        s_c = -scale[0] * rn;          // fold -scale and 1/||x|| into one constant
    }

    // ---- In-place fast Walsh-Hadamard transform (natural order) ----
    // y[j] = sum_i x[i] * (-1)^popcount(i&j)
#pragma unroll
    for (int h = 1; h < IN_DIM; h <<= 1) {
        __syncthreads();
#pragma unroll
        for (int k = 0; k < IN_DIM / 2 / THREADS; ++k) {  // 4 pairs per thread
            int p = tid + k * THREADS;
            int i = ((p & ~(h - 1)) << 1) | (p & (h - 1));
            float a = s[i];
            float b = s[i + h];
            s[i]     = a + b;
            s[i + h] = a - b;
        }
    }
    __syncthreads();

    // ---- Epilogue: out[row, j] = c * y[j & 2047] + bias[j] ----
    const float c = s_c;
    float* __restrict__ orow = out + (size_t)row * OUT_DIM;
#pragma unroll 4
    for (int j = tid; j < OUT_DIM; j += THREADS) {
        orow[j] = fmaf(c, s[j & (IN_DIM - 1)], __ldg(&bias[j]));
    }
}

extern "C" void kernel_launch(void* const* d_in, const int* in_sizes, int n_in,
                              void* d_out, int out_size)
{
    const float* x     = (const float*)d_in[0];   // [4096, 2048]
    const float* scale = (const float*)d_in[1];   // [1]
    const float* bias  = (const float*)d_in[2];   // [14951]
    float* out = (float*)d_out;                   // [4096, 14951]

    const int batch = in_sizes[0] / IN_DIM;       // 4096
    hadamard_classifier_kernel<<<batch, THREADS>>>(x, scale, bias, out);
}